// round 4
// baseline (speedup 1.0000x reference)
#include <cuda_runtime.h>
#include <cstdint>

#define BB    32
#define NN    1024
#define ND    14
#define HID   64
#define HEADD 128
#define MAXN  64
#define ROWS  (BB*NN)          // 32768
#define RPB   32               // rows per block in agg kernels
#define NBLK  (ROWS/RPB)       // 1024
#define PAD   66               // padded h-row stride (floats)

// ---------------- scratch (device globals; no allocations) ----------------
__device__ unsigned short g_nbr[ROWS * MAXN];   // ELL neighbor lists (cols < 1024)
__device__ int   g_cnt[ROWS];
__device__ float g_dinv[ROWS];
__device__ float g_bufA[ROWS * HID];
__device__ float g_bufB[ROWS * HID];
__device__ float g_pool[NBLK * HID];            // per-block pool partials

// ---------------------------------------------------------------------------
// K1: one warp per adjacency row. Load 8 float4 up-front (MLP=8), warp-scan,
// store uint16 ELL list + dinv. 128MB read once -> HBM-bound.
// ---------------------------------------------------------------------------
__global__ void k_adj(const float4* __restrict__ adj4) {
    int gtid = blockIdx.x * blockDim.x + threadIdx.x;
    int row  = gtid >> 5;
    int lane = gtid & 31;
    if (row >= ROWS) return;

    const float4* rp = adj4 + (size_t)row * (NN / 4);
    float4 v[8];
    #pragma unroll
    for (int k = 0; k < 8; ++k) v[k] = rp[k * 32 + lane];

    int base = row * MAXN;
    int cnt = 0;
    #pragma unroll
    for (int k = 0; k < 8; ++k) {
        int col0 = (k * 32 + lane) * 4;
        int m = (v[k].x != 0.f ? 1 : 0) | (v[k].y != 0.f ? 2 : 0)
              | (v[k].z != 0.f ? 4 : 0) | (v[k].w != 0.f ? 8 : 0);
        int c = __popc(m);
        int x = c;
        #pragma unroll
        for (int d = 1; d < 32; d <<= 1) {
            int y = __shfl_up_sync(0xffffffffu, x, d);
            if (lane >= d) x += y;
        }
        int w   = cnt + x - c;
        int tot = __shfl_sync(0xffffffffu, x, 31);
        if (m & 1) { if (w < MAXN) g_nbr[base + w] = (unsigned short)col0;       w++; }
        if (m & 2) { if (w < MAXN) g_nbr[base + w] = (unsigned short)(col0 + 1); w++; }
        if (m & 4) { if (w < MAXN) g_nbr[base + w] = (unsigned short)(col0 + 2); w++; }
        if (m & 8) { if (w < MAXN) g_nbr[base + w] = (unsigned short)(col0 + 3); w++; }
        cnt += tot;
    }
    if (lane == 0) {
        g_cnt[row]  = cnt;
        g_dinv[row] = rsqrtf((float)(cnt > 0 ? cnt : 1));
    }
}

// ---------------------------------------------------------------------------
// K2: z0[row] = dinv[row] * (x[row] @ W1). 64 rows / 256-thread block.
// ---------------------------------------------------------------------------
__global__ void __launch_bounds__(256) k_lin0(const float* __restrict__ x,
                                              const float* __restrict__ W1,
                                              float* __restrict__ out) {
    int tid = threadIdx.x;
    int g   = tid >> 6;
    int t   = tid & 63;
    int R0  = blockIdx.x * 64;

    __shared__ float sx[64 * ND];
    __shared__ float sdinv[64];

    float wreg[ND];
    #pragma unroll
    for (int c = 0; c < ND; ++c) wreg[c] = W1[c * HID + t];

    for (int i = tid; i < 64 * ND; i += 256) sx[i] = x[(size_t)R0 * ND + i];
    if (tid < 64) sdinv[tid] = g_dinv[R0 + tid];
    __syncthreads();

    #pragma unroll 4
    for (int rr = 0; rr < 16; ++rr) {
        int r = g * 16 + rr;
        const float* xr = sx + r * ND;
        float a = 0.f;
        #pragma unroll
        for (int c = 0; c < ND; ++c) a = fmaf(xr[c], wreg[c], a);
        out[(size_t)(R0 + r) * HID + t] = a * sdinv[r];
    }
}

// ---------------------------------------------------------------------------
// K3: fused aggregation layer, 32 rows / 256-thread block.
//  Phase 1: warp w handles rows w*4..w*4+3 INTERLEAVED (lane = channel pair,
//           float2 gather; per-row predicates are warp-uniform) -> MLP ~8-16.
//           relu -> smem (HAS_MV) or pool partial (!HAS_MV).
//  Phase 2 (HAS_MV): 32x64x64 micro-GEMM, thread = 2 rows x 4 cols.
// ---------------------------------------------------------------------------
template <int HAS_MV>
__global__ void __launch_bounds__(256) k_agg(const float* __restrict__ zin,
                                             const float* __restrict__ bias,
                                             const float* __restrict__ Wnext,
                                             float* __restrict__ out) {
    int tid  = threadIdx.x;
    int w    = tid >> 5;
    int lane = tid & 31;
    int R0   = blockIdx.x * RPB;
    int bbase = (R0 >> 10) << 10;                 // batch * N

    __shared__ unsigned short sidx[RPB * MAXN];   // 4 KB
    __shared__ float sh[RPB * PAD];               // 8.25 KB
    __shared__ float sW[HID * HID];               // 16 KB
    __shared__ float sdinv[RPB];
    __shared__ int   scnt[RPB];
    __shared__ float2 spart[8][32];

    // ---- stage: ELL lists (int4), W (float4), dinv, cnt ----
    {
        const int4* src = (const int4*)(g_nbr + (size_t)R0 * MAXN);
        int4* dst = (int4*)sidx;
        dst[tid] = src[tid];                      // 256 * 16B = 4KB exactly
        if (HAS_MV) {
            const float4* ws = (const float4*)Wnext;
            float4* wd = (float4*)sW;
            #pragma unroll
            for (int i = 0; i < HID * HID / 4 / 256; ++i)
                wd[tid + i * 256] = ws[tid + i * 256];
        }
        if (tid < RPB) {
            int c = g_cnt[R0 + tid];
            scnt[tid]  = c > MAXN ? MAXN : c;
            sdinv[tid] = g_dinv[R0 + tid];
        }
    }
    __syncthreads();

    // ---- phase 1: 4 rows per warp, interleaved gather ----
    const float2 breg = ((const float2*)bias)[lane];
    const float2* zb = (const float2*)zin + (size_t)bbase * (HID / 2) + lane;

    int r0 = w * 4;
    int c0 = scnt[r0], c1 = scnt[r0 + 1], c2 = scnt[r0 + 2], c3 = scnt[r0 + 3];
    const unsigned short* i0 = sidx + (r0    ) * MAXN;
    const unsigned short* i1 = sidx + (r0 + 1) * MAXN;
    const unsigned short* i2 = sidx + (r0 + 2) * MAXN;
    const unsigned short* i3 = sidx + (r0 + 3) * MAXN;

    float2 a0 = make_float2(0.f, 0.f), a1 = a0, a2 = a0, a3 = a0;
    int cmax = max(max(c0, c1), max(c2, c3));

    #pragma unroll 2
    for (int k = 0; k < cmax; ++k) {
        if (k < c0) { float2 v = zb[i0[k] * (HID / 2)]; a0.x += v.x; a0.y += v.y; }
        if (k < c1) { float2 v = zb[i1[k] * (HID / 2)]; a1.x += v.x; a1.y += v.y; }
        if (k < c2) { float2 v = zb[i2[k] * (HID / 2)]; a2.x += v.x; a2.y += v.y; }
        if (k < c3) { float2 v = zb[i3[k] * (HID / 2)]; a3.x += v.x; a3.y += v.y; }
    }

    float d0 = sdinv[r0], d1 = sdinv[r0 + 1], d2 = sdinv[r0 + 2], d3 = sdinv[r0 + 3];
    float2 h0, h1, h2, h3;
    h0.x = fmaxf(fmaf(d0, a0.x, breg.x), 0.f); h0.y = fmaxf(fmaf(d0, a0.y, breg.y), 0.f);
    h1.x = fmaxf(fmaf(d1, a1.x, breg.x), 0.f); h1.y = fmaxf(fmaf(d1, a1.y, breg.y), 0.f);
    h2.x = fmaxf(fmaf(d2, a2.x, breg.x), 0.f); h2.y = fmaxf(fmaf(d2, a2.y, breg.y), 0.f);
    h3.x = fmaxf(fmaf(d3, a3.x, breg.x), 0.f); h3.y = fmaxf(fmaf(d3, a3.y, breg.y), 0.f);

    if (HAS_MV) {
        *(float2*)(sh + (r0    ) * PAD + 2 * lane) = h0;
        *(float2*)(sh + (r0 + 1) * PAD + 2 * lane) = h1;
        *(float2*)(sh + (r0 + 2) * PAD + 2 * lane) = h2;
        *(float2*)(sh + (r0 + 3) * PAD + 2 * lane) = h3;
    } else {
        float2 p;
        p.x = (h0.x + h1.x) + (h2.x + h3.x);
        p.y = (h0.y + h1.y) + (h2.y + h3.y);
        spart[w][lane] = p;
        __syncthreads();
        if (tid < 32) {
            float2 s = spart[0][tid];
            #pragma unroll
            for (int i = 1; i < 8; ++i) { s.x += spart[i][tid].x; s.y += spart[i][tid].y; }
            *(float2*)(out + blockIdx.x * HID + 2 * tid) = s;
        }
        return;
    }

    __syncthreads();

    // ---- phase 2: 32x64x64 micro-GEMM, 2 rows x 4 cols per thread ----
    {
        int tx = tid & 15;          // cols 4*tx .. 4*tx+3
        int ty = tid >> 4;          // rows 2*ty, 2*ty+1

        float acc[2][4];
        #pragma unroll
        for (int i = 0; i < 2; ++i)
            #pragma unroll
            for (int j = 0; j < 4; ++j) acc[i][j] = 0.f;

        const float* shb = sh + (2 * ty) * PAD;
        #pragma unroll 4
        for (int c = 0; c < HID; ++c) {
            float4 wv = *(const float4*)(sW + c * HID + 4 * tx);
            float b0 = shb[c];
            float b1 = shb[PAD + c];
            acc[0][0] = fmaf(b0, wv.x, acc[0][0]);
            acc[0][1] = fmaf(b0, wv.y, acc[0][1]);
            acc[0][2] = fmaf(b0, wv.z, acc[0][2]);
            acc[0][3] = fmaf(b0, wv.w, acc[0][3]);
            acc[1][0] = fmaf(b1, wv.x, acc[1][0]);
            acc[1][1] = fmaf(b1, wv.y, acc[1][1]);
            acc[1][2] = fmaf(b1, wv.z, acc[1][2]);
            acc[1][3] = fmaf(b1, wv.w, acc[1][3]);
        }

        #pragma unroll
        for (int i = 0; i < 2; ++i) {
            int r = 2 * ty + i;
            float di = sdinv[r];
            float4 o;
            o.x = di * acc[i][0];
            o.y = di * acc[i][1];
            o.z = di * acc[i][2];
            o.w = di * acc[i][3];
            *(float4*)(out + (size_t)(R0 + r) * HID + 4 * tx) = o;
        }
    }
}

// ---------------------------------------------------------------------------
// K4: per batch: pooled = mean of 32 block partials; relu(pooled@Wf1+bf1)@Wf2+bf2
// ---------------------------------------------------------------------------
__global__ void k_final(const float* __restrict__ pool,
                        const float* __restrict__ Wf1, const float* __restrict__ bf1,
                        const float* __restrict__ Wf2, const float* __restrict__ bf2,
                        float* __restrict__ out) {
    int b   = blockIdx.x;
    int tid = threadIdx.x;           // 128 threads
    __shared__ float pooled[HID];
    __shared__ float hred[HEADD];

    if (tid < HID) {
        float s = 0.f;
        #pragma unroll
        for (int i = 0; i < NN / RPB; ++i)
            s += pool[(b * (NN / RPB) + i) * HID + tid];
        pooled[tid] = s * (1.f / NN);
    }
    __syncthreads();

    float a = bf1[tid];
    #pragma unroll
    for (int c = 0; c < HID; ++c) a = fmaf(pooled[c], Wf1[c * HEADD + tid], a);
    hred[tid] = fmaxf(a, 0.f) * Wf2[tid];
    __syncthreads();

    if (tid < 32) {
        float s = hred[tid] + hred[tid + 32] + hred[tid + 64] + hred[tid + 96];
        #pragma unroll
        for (int d = 16; d; d >>= 1) s += __shfl_down_sync(0xffffffffu, s, d);
        if (tid == 0) out[b] = s + bf2[0];
    }
}

// ---------------------------------------------------------------------------
extern "C" void kernel_launch(void* const* d_in, const int* in_sizes, int n_in,
                              void* d_out, int out_size) {
    const float* x    = (const float*)d_in[0];
    const float* adj  = (const float*)d_in[1];
    const float* W1   = (const float*)d_in[2];
    const float* b1   = (const float*)d_in[3];
    const float* W2   = (const float*)d_in[4];
    const float* b2   = (const float*)d_in[5];
    const float* W3   = (const float*)d_in[6];
    const float* b3   = (const float*)d_in[7];
    const float* Wf1  = (const float*)d_in[8];
    const float* bf1  = (const float*)d_in[9];
    const float* Wf2  = (const float*)d_in[10];
    const float* bf2  = (const float*)d_in[11];
    float* out = (float*)d_out;

    float *bufA, *bufB, *pool;
    cudaGetSymbolAddress((void**)&bufA, g_bufA);
    cudaGetSymbolAddress((void**)&bufB, g_bufB);
    cudaGetSymbolAddress((void**)&pool, g_pool);

    k_adj<<<ROWS * 32 / 256, 256>>>((const float4*)adj);       // ELL + dinv
    k_lin0<<<ROWS / 64, 256>>>(x, W1, bufA);                   // z0
    k_agg<1><<<NBLK, 256>>>(bufA, b1, W2, bufB);               // layer1 -> z1
    k_agg<1><<<NBLK, 256>>>(bufB, b2, W3, bufA);               // layer2 -> z2
    k_agg<0><<<NBLK, 256>>>(bufA, b3, nullptr, pool);          // layer3 -> pool partials
    k_final<<<BB, HEADD>>>(pool, Wf1, bf1, Wf2, bf2, out);     // head
}

// round 5
// speedup vs baseline: 1.1272x; 1.1272x over previous
#include <cuda_runtime.h>
#include <cstdint>

#define BB    32
#define NN    1024
#define ND    14
#define HID   64
#define HEADD 128
#define MAXN  64
#define ROWS  (BB*NN)          // 32768
#define RPB   64               // rows per block in agg kernels
#define NBLK  (ROWS/RPB)       // 512
#define PAD   66               // padded h-row stride (floats)

typedef unsigned long long ull;

#define FMA2(d, a, b, c) \
    asm("fma.rn.f32x2 %0, %1, %2, %3;" : "=l"(d) : "l"(a), "l"(b), "l"(c))
#define ADD2(d, a, b) \
    asm("add.rn.f32x2 %0, %1, %2;" : "=l"(d) : "l"(a), "l"(b))
#define PACK2(d, lo, hi) \
    asm("mov.b64 %0, {%1, %2};" : "=l"(d) : "f"(lo), "f"(hi))
#define DUP2(d, s) \
    asm("mov.b64 %0, {%1, %1};" : "=l"(d) : "f"(s))
#define UNPACK2(lo, hi, s) \
    asm("mov.b64 {%0, %1}, %2;" : "=f"(lo), "=f"(hi) : "l"(s))

// ---------------- scratch (device globals; no allocations) ----------------
__device__ unsigned short g_nbr[ROWS * MAXN];   // ELL neighbor lists (cols < 1024)
__device__ int   g_cnt[ROWS];
__device__ float g_dinv[ROWS];
__device__ float g_bufA[ROWS * HID];
__device__ float g_bufB[ROWS * HID];
__device__ float g_pool[NBLK * HID];            // per-block pool partials

// ---------------------------------------------------------------------------
// K1: one warp per adjacency row. Load 8 float4 up-front (MLP=8), warp-scan,
// store uint16 ELL list + dinv. 128MB read once -> HBM-bound (~16-20us).
// ---------------------------------------------------------------------------
__global__ void k_adj(const float4* __restrict__ adj4) {
    int gtid = blockIdx.x * blockDim.x + threadIdx.x;
    int row  = gtid >> 5;
    int lane = gtid & 31;
    if (row >= ROWS) return;

    const float4* rp = adj4 + (size_t)row * (NN / 4);
    float4 v[8];
    #pragma unroll
    for (int k = 0; k < 8; ++k) v[k] = rp[k * 32 + lane];

    int base = row * MAXN;
    int cnt = 0;
    #pragma unroll
    for (int k = 0; k < 8; ++k) {
        int col0 = (k * 32 + lane) * 4;
        int m = (v[k].x != 0.f ? 1 : 0) | (v[k].y != 0.f ? 2 : 0)
              | (v[k].z != 0.f ? 4 : 0) | (v[k].w != 0.f ? 8 : 0);
        int c = __popc(m);
        int x = c;
        #pragma unroll
        for (int d = 1; d < 32; d <<= 1) {
            int y = __shfl_up_sync(0xffffffffu, x, d);
            if (lane >= d) x += y;
        }
        int w   = cnt + x - c;
        int tot = __shfl_sync(0xffffffffu, x, 31);
        if (m & 1) { if (w < MAXN) g_nbr[base + w] = (unsigned short)col0;       w++; }
        if (m & 2) { if (w < MAXN) g_nbr[base + w] = (unsigned short)(col0 + 1); w++; }
        if (m & 4) { if (w < MAXN) g_nbr[base + w] = (unsigned short)(col0 + 2); w++; }
        if (m & 8) { if (w < MAXN) g_nbr[base + w] = (unsigned short)(col0 + 3); w++; }
        cnt += tot;
    }
    if (lane == 0) {
        g_cnt[row]  = cnt;
        g_dinv[row] = rsqrtf((float)(cnt > 0 ? cnt : 1));
    }
}

// ---------------------------------------------------------------------------
// K2: z0[row] = dinv[row] * (x[row] @ W1). 64 rows / 256-thread block.
// ---------------------------------------------------------------------------
__global__ void __launch_bounds__(256) k_lin0(const float* __restrict__ x,
                                              const float* __restrict__ W1,
                                              float* __restrict__ out) {
    int tid = threadIdx.x;
    int g   = tid >> 6;
    int t   = tid & 63;
    int R0  = blockIdx.x * 64;

    __shared__ float sx[64 * ND];
    __shared__ float sdinv[64];

    float wreg[ND];
    #pragma unroll
    for (int c = 0; c < ND; ++c) wreg[c] = W1[c * HID + t];

    for (int i = tid; i < 64 * ND; i += 256) sx[i] = x[(size_t)R0 * ND + i];
    if (tid < 64) sdinv[tid] = g_dinv[R0 + tid];
    __syncthreads();

    #pragma unroll 4
    for (int rr = 0; rr < 16; ++rr) {
        int r = g * 16 + rr;
        const float* xr = sx + r * ND;
        float a = 0.f;
        #pragma unroll
        for (int c = 0; c < ND; ++c) a = fmaf(xr[c], wreg[c], a);
        out[(size_t)(R0 + r) * HID + t] = a * sdinv[r];
    }
}

// ---------------------------------------------------------------------------
// K3: fused aggregation layer, 64 rows / 256-thread block.
//  Phase 1: warp w handles rows w*8..w*8+7 interleaved; lane = channel pair;
//           gather via LDG.64, packed add.rn.f32x2 accumulators. relu ->
//           padded smem (HAS_MV) or pool partial (!HAS_MV).
//  Phase 2 (HAS_MV): 64x64x64 micro-GEMM, thread tile 4 rows x 4 cols,
//           packed fma.rn.f32x2 (8 FMA2 per c), W via LDS.128 (ty-pair
//           broadcast merged), h scalar broadcast.
// ---------------------------------------------------------------------------
template <int HAS_MV>
__global__ void __launch_bounds__(256, 4) k_agg(const float* __restrict__ zin,
                                                const float* __restrict__ bias,
                                                const float* __restrict__ Wnext,
                                                float* __restrict__ out) {
    int tid  = threadIdx.x;
    int w    = tid >> 5;
    int lane = tid & 31;
    int R0   = blockIdx.x * RPB;
    int bbase = (R0 >> 10) << 10;                 // batch * N

    __shared__ unsigned short sidx[RPB * MAXN];   // 8 KB
    __shared__ float sh[HAS_MV ? RPB * PAD : 1];  // 16.9 KB
    __shared__ float sW[HAS_MV ? HID * HID : 1];  // 16 KB
    __shared__ float sdinv[RPB];
    __shared__ int   scnt[RPB];
    __shared__ float2 spart[8][32];

    // ---- stage: ELL lists (int4), W (float4), dinv, cnt ----
    {
        const int4* src = (const int4*)(g_nbr + (size_t)R0 * MAXN);
        int4* dst = (int4*)sidx;
        #pragma unroll
        for (int i = 0; i < RPB * MAXN * 2 / 16 / 256; ++i)   // 2 iters
            dst[tid + i * 256] = src[tid + i * 256];
        if (HAS_MV) {
            const float4* ws = (const float4*)Wnext;
            float4* wd = (float4*)sW;
            #pragma unroll
            for (int i = 0; i < HID * HID / 4 / 256; ++i)     // 4 iters
                wd[tid + i * 256] = ws[tid + i * 256];
        }
        if (tid < RPB) {
            int c = g_cnt[R0 + tid];
            scnt[tid]  = c > MAXN ? MAXN : c;
            sdinv[tid] = g_dinv[R0 + tid];
        }
    }
    __syncthreads();

    // ---- phase 1: 8 rows per warp, interleaved gather, packed adds ----
    {
        const float2 bf = ((const float2*)bias)[lane];
        ull breg; PACK2(breg, bf.x, bf.y);
        const ull* zb = (const ull*)zin + (size_t)bbase * (HID / 2) + lane;

        int r0 = w * 8;
        int cn[8];
        const unsigned short* ip[8];
        ull acc[8];
        #pragma unroll
        for (int i = 0; i < 8; ++i) {
            cn[i]  = scnt[r0 + i];
            ip[i]  = sidx + (r0 + i) * MAXN;
            acc[i] = 0ull;
        }
        int cmax = 0;
        #pragma unroll
        for (int i = 0; i < 8; ++i) cmax = max(cmax, cn[i]);

        for (int k = 0; k < cmax; ++k) {
            #pragma unroll
            for (int i = 0; i < 8; ++i) {
                if (k < cn[i]) {
                    ull v = zb[ip[i][k] * (HID / 2)];
                    ADD2(acc[i], acc[i], v);
                }
            }
        }

        float2 pacc = make_float2(0.f, 0.f);
        #pragma unroll
        for (int i = 0; i < 8; ++i) {
            float ax, ay;
            UNPACK2(ax, ay, acc[i]);
            float di = sdinv[r0 + i];
            float bx, by;
            UNPACK2(bx, by, breg);
            float hx = fmaxf(fmaf(di, ax, bx), 0.f);
            float hy = fmaxf(fmaf(di, ay, by), 0.f);
            if (HAS_MV) {
                *(float2*)(sh + (r0 + i) * PAD + 2 * lane) = make_float2(hx, hy);
            } else {
                pacc.x += hx; pacc.y += hy;
            }
        }

        if (!HAS_MV) {
            spart[w][lane] = pacc;
            __syncthreads();
            if (tid < 32) {
                float2 s = spart[0][tid];
                #pragma unroll
                for (int i = 1; i < 8; ++i) { s.x += spart[i][tid].x; s.y += spart[i][tid].y; }
                *(float2*)(out + blockIdx.x * HID + 2 * tid) = s;
            }
            return;
        }
    }

    __syncthreads();

    // ---- phase 2: 64x64x64 micro-GEMM, 4 rows x 4 cols per thread, FMA2 ----
    {
        int tx = tid & 15;          // cols 4*tx .. 4*tx+3
        int ty = tid >> 4;          // rows 4*ty .. 4*ty+3

        ull acc[4][2];
        #pragma unroll
        for (int i = 0; i < 4; ++i) { acc[i][0] = 0ull; acc[i][1] = 0ull; }

        const float* shb = sh + (4 * ty) * PAD;
        #pragma unroll 4
        for (int c = 0; c < HID; ++c) {
            ulonglong2 wv = *(const ulonglong2*)(sW + c * HID + 4 * tx);
            #pragma unroll
            for (int i = 0; i < 4; ++i) {
                float hv = shb[i * PAD + c];
                ull hh; DUP2(hh, hv);
                FMA2(acc[i][0], hh, wv.x, acc[i][0]);
                FMA2(acc[i][1], hh, wv.y, acc[i][1]);
            }
        }

        #pragma unroll
        for (int i = 0; i < 4; ++i) {
            int r = 4 * ty + i;
            float di = sdinv[r];
            float a0, a1, a2, a3;
            UNPACK2(a0, a1, acc[i][0]);
            UNPACK2(a2, a3, acc[i][1]);
            float4 o;
            o.x = di * a0; o.y = di * a1; o.z = di * a2; o.w = di * a3;
            *(float4*)(out + (size_t)(R0 + r) * HID + 4 * tx) = o;
        }
    }
}

// ---------------------------------------------------------------------------
// K4: per batch: pooled = mean of 16 block partials; relu(pooled@Wf1+bf1)@Wf2+bf2
// ---------------------------------------------------------------------------
__global__ void k_final(const float* __restrict__ pool,
                        const float* __restrict__ Wf1, const float* __restrict__ bf1,
                        const float* __restrict__ Wf2, const float* __restrict__ bf2,
                        float* __restrict__ out) {
    int b   = blockIdx.x;
    int tid = threadIdx.x;           // 128 threads
    __shared__ float pooled[HID];
    __shared__ float hred[HEADD];

    if (tid < HID) {
        float s = 0.f;
        #pragma unroll
        for (int i = 0; i < NN / RPB; ++i)
            s += pool[(b * (NN / RPB) + i) * HID + tid];
        pooled[tid] = s * (1.f / NN);
    }
    __syncthreads();

    float a = bf1[tid];
    #pragma unroll
    for (int c = 0; c < HID; ++c) a = fmaf(pooled[c], Wf1[c * HEADD + tid], a);
    hred[tid] = fmaxf(a, 0.f) * Wf2[tid];
    __syncthreads();

    if (tid < 32) {
        float s = hred[tid] + hred[tid + 32] + hred[tid + 64] + hred[tid + 96];
        #pragma unroll
        for (int d = 16; d; d >>= 1) s += __shfl_down_sync(0xffffffffu, s, d);
        if (tid == 0) out[b] = s + bf2[0];
    }
}

// ---------------------------------------------------------------------------
extern "C" void kernel_launch(void* const* d_in, const int* in_sizes, int n_in,
                              void* d_out, int out_size) {
    const float* x    = (const float*)d_in[0];
    const float* adj  = (const float*)d_in[1];
    const float* W1   = (const float*)d_in[2];
    const float* b1   = (const float*)d_in[3];
    const float* W2   = (const float*)d_in[4];
    const float* b2   = (const float*)d_in[5];
    const float* W3   = (const float*)d_in[6];
    const float* b3   = (const float*)d_in[7];
    const float* Wf1  = (const float*)d_in[8];
    const float* bf1  = (const float*)d_in[9];
    const float* Wf2  = (const float*)d_in[10];
    const float* bf2  = (const float*)d_in[11];
    float* out = (float*)d_out;

    float *bufA, *bufB, *pool;
    cudaGetSymbolAddress((void**)&bufA, g_bufA);
    cudaGetSymbolAddress((void**)&bufB, g_bufB);
    cudaGetSymbolAddress((void**)&pool, g_pool);

    k_adj<<<ROWS * 32 / 256, 256>>>((const float4*)adj);       // ELL + dinv
    k_lin0<<<ROWS / 64, 256>>>(x, W1, bufA);                   // z0
    k_agg<1><<<NBLK, 256>>>(bufA, b1, W2, bufB);               // layer1 -> z1
    k_agg<1><<<NBLK, 256>>>(bufB, b2, W3, bufA);               // layer2 -> z2
    k_agg<0><<<NBLK, 256>>>(bufA, b3, nullptr, pool);          // layer3 -> pool partials
    k_final<<<BB, HEADD>>>(pool, Wf1, bf1, Wf2, bf2, out);     // head
}